// round 1
// baseline (speedup 1.0000x reference)
#include <cuda_runtime.h>
#include <cuda_bf16.h>
#include <math.h>

#define B_ROWS   4096
#define D_EMBED  128
#define TWO_B    8192
#define INV_T    2.0f     // 1 / 0.5
#define EPS_N    1e-8f

// Scratch (device globals: allocation-free rule)
__device__ float g_Z[TWO_B * D_EMBED];   // normalized [z_i; z_j], 4 MB
__device__ float g_rowsum[TWO_B];        // sum_j exp(sim/T) excluding diagonal
__device__ float g_pos[B_ROWS];          // dot(z_i, z_j) per pair

// ---------------------------------------------------------------------------
// K0: normalize rows, compute positives, zero row sums
// grid = B_ROWS blocks, 128 threads (one thread per embed element)
// ---------------------------------------------------------------------------
__global__ void k_normalize(const float* __restrict__ p1,
                            const float* __restrict__ p2) {
    const int row = blockIdx.x;
    const int t   = threadIdx.x;

    float a = p1[row * D_EMBED + t];
    float b = p2[row * D_EMBED + t];

    float aa = a * a, bb = b * b, ab = a * b;
    // warp-level reduce
    #pragma unroll
    for (int off = 16; off > 0; off >>= 1) {
        aa += __shfl_xor_sync(0xffffffffu, aa, off);
        bb += __shfl_xor_sync(0xffffffffu, bb, off);
        ab += __shfl_xor_sync(0xffffffffu, ab, off);
    }
    __shared__ float s[3][4];
    const int warp = t >> 5;
    if ((t & 31) == 0) { s[0][warp] = aa; s[1][warp] = bb; s[2][warp] = ab; }
    __syncthreads();
    const float saa = s[0][0] + s[0][1] + s[0][2] + s[0][3];
    const float sbb = s[1][0] + s[1][1] + s[1][2] + s[1][3];
    const float sab = s[2][0] + s[2][1] + s[2][2] + s[2][3];

    const float n1 = fmaxf(sqrtf(saa), EPS_N);
    const float n2 = fmaxf(sqrtf(sbb), EPS_N);

    g_Z[row * D_EMBED + t]            = a / n1;
    g_Z[(B_ROWS + row) * D_EMBED + t] = b / n2;

    if (t == 0) {
        g_pos[row]             = sab / (n1 * n2);
        g_rowsum[row]          = 0.0f;
        g_rowsum[B_ROWS + row] = 0.0f;
    }
}

// ---------------------------------------------------------------------------
// K1: tiled sim = Z*Z^T, fused exp(sim/T) + masked row-sum
// 64x64 tile per 256-thread block, 4x4 micro-tile, K=128 in two 64-chunks.
// Smem stored k-major so compute loads are conflict-free LDS.128.
// grid = (128, 128)
// ---------------------------------------------------------------------------
#define BT 64   // tile dim
#define BK 64   // k chunk

__global__ __launch_bounds__(256) void k_sim(void) {
    __shared__ float As[BK][BT];   // [k][m] 16 KB
    __shared__ float Bs[BK][BT];   // [k][n] 16 KB

    const int tid = threadIdx.x;
    const int tx  = tid & 15;        // 0..15 -> 4 cols each
    const int ty  = tid >> 4;        // 0..15 -> 4 rows each
    const int I   = blockIdx.y * BT; // row tile base
    const int J   = blockIdx.x * BT; // col tile base

    float acc[4][4];
    #pragma unroll
    for (int i = 0; i < 4; i++)
        #pragma unroll
        for (int j = 0; j < 4; j++) acc[i][j] = 0.0f;

    const int lr = tid & 63;   // row within tile for loading
    const int lg = tid >> 6;   // 0..3 load group

    for (int kc = 0; kc < D_EMBED; kc += BK) {
        // load A tile (rows I..I+63, cols kc..kc+63) transposed into As[k][m]
        #pragma unroll
        for (int m = 0; m < 4; m++) {
            const int k4 = lg * 4 + m;           // float4 index 0..15
            float4 va = *reinterpret_cast<const float4*>(
                &g_Z[(I + lr) * D_EMBED + kc + k4 * 4]);
            As[k4 * 4 + 0][lr] = va.x;
            As[k4 * 4 + 1][lr] = va.y;
            As[k4 * 4 + 2][lr] = va.z;
            As[k4 * 4 + 3][lr] = va.w;
            float4 vb = *reinterpret_cast<const float4*>(
                &g_Z[(J + lr) * D_EMBED + kc + k4 * 4]);
            Bs[k4 * 4 + 0][lr] = vb.x;
            Bs[k4 * 4 + 1][lr] = vb.y;
            Bs[k4 * 4 + 2][lr] = vb.z;
            Bs[k4 * 4 + 3][lr] = vb.w;
        }
        __syncthreads();

        #pragma unroll
        for (int k = 0; k < BK; k++) {
            const float4 av = *reinterpret_cast<const float4*>(&As[k][ty * 4]);
            const float4 bv = *reinterpret_cast<const float4*>(&Bs[k][tx * 4]);
            const float a0 = av.x, a1 = av.y, a2 = av.z, a3 = av.w;
            const float b0 = bv.x, b1 = bv.y, b2 = bv.z, b3 = bv.w;
            acc[0][0] = fmaf(a0, b0, acc[0][0]);
            acc[0][1] = fmaf(a0, b1, acc[0][1]);
            acc[0][2] = fmaf(a0, b2, acc[0][2]);
            acc[0][3] = fmaf(a0, b3, acc[0][3]);
            acc[1][0] = fmaf(a1, b0, acc[1][0]);
            acc[1][1] = fmaf(a1, b1, acc[1][1]);
            acc[1][2] = fmaf(a1, b2, acc[1][2]);
            acc[1][3] = fmaf(a1, b3, acc[1][3]);
            acc[2][0] = fmaf(a2, b0, acc[2][0]);
            acc[2][1] = fmaf(a2, b1, acc[2][1]);
            acc[2][2] = fmaf(a2, b2, acc[2][2]);
            acc[2][3] = fmaf(a2, b3, acc[2][3]);
            acc[3][0] = fmaf(a3, b0, acc[3][0]);
            acc[3][1] = fmaf(a3, b1, acc[3][1]);
            acc[3][2] = fmaf(a3, b2, acc[3][2]);
            acc[3][3] = fmaf(a3, b3, acc[3][3]);
        }
        __syncthreads();
    }

    // epilogue: exp(sim/T), mask diagonal, per-thread row partials
    float rs[4];
    #pragma unroll
    for (int i = 0; i < 4; i++) {
        const int gi = I + ty * 4 + i;
        float r = 0.0f;
        #pragma unroll
        for (int j = 0; j < 4; j++) {
            const int gj = J + tx * 4 + j;
            const float e = __expf(INV_T * acc[i][j]);
            r += (gi == gj) ? 0.0f : e;
        }
        rs[i] = r;
    }
    // reduce across tx (16 threads = half warp; ty is fixed within the group)
    #pragma unroll
    for (int i = 0; i < 4; i++) {
        #pragma unroll
        for (int off = 1; off < 16; off <<= 1)
            rs[i] += __shfl_xor_sync(0xffffffffu, rs[i], off);
    }
    if (tx == 0) {
        #pragma unroll
        for (int i = 0; i < 4; i++)
            atomicAdd(&g_rowsum[I + ty * 4 + i], rs[i]);
    }
}

// ---------------------------------------------------------------------------
// K2: loss = sum_i [log(denom_i) - pos_i/T] / (2B)
// ---------------------------------------------------------------------------
__global__ void k_finalize(float* __restrict__ out) {
    __shared__ double sd[1024];
    const int t = threadIdx.x;
    double local = 0.0;
    for (int i = t; i < TWO_B; i += 1024) {
        const double denom = (double)g_rowsum[i];
        const double pos   = (double)g_pos[i & (B_ROWS - 1)];
        local += log(denom) - (double)INV_T * pos;
    }
    sd[t] = local;
    __syncthreads();
    for (int off = 512; off > 0; off >>= 1) {
        if (t < off) sd[t] += sd[t + off];
        __syncthreads();
    }
    if (t == 0) out[0] = (float)(sd[0] / (double)TWO_B);
}

// ---------------------------------------------------------------------------
extern "C" void kernel_launch(void* const* d_in, const int* in_sizes, int n_in,
                              void* d_out, int out_size) {
    const float* p1 = (const float*)d_in[0];
    const float* p2 = (const float*)d_in[1];
    float* out = (float*)d_out;

    k_normalize<<<B_ROWS, D_EMBED>>>(p1, p2);
    dim3 grid(TWO_B / BT, TWO_B / BT);
    k_sim<<<grid, 256>>>();
    k_finalize<<<1, 1024>>>(out);
}

// round 6
// speedup vs baseline: 3.4407x; 3.4407x over previous
#include <cuda_runtime.h>
#include <cuda_bf16.h>
#include <mma.h>
#include <cstdint>
#include <math.h>

using namespace nvcuda;

#define B_ROWS   4096
#define D_EMBED  128
#define TWO_B    8192
#define INV_T    2.0f
#define EPS_N    1e-8f

#define TILE     128          // CTA tile (M and N)
#define LDAB     136          // bf16 leading dim for A/B smem (272B, 16B-mult)
#define LDC      132          // fp32 leading dim for C smem
#define SMEM_AB  (2 * TILE * LDAB * 2)   // 69632 B
#define SMEM_C   (TILE * LDC * 4)        // 67584 B
#define SMEM_TOTAL (SMEM_AB > SMEM_C ? SMEM_AB : SMEM_C)

// Scratch (device globals: allocation-free rule)
__device__ __align__(16) __nv_bfloat16 g_Zh[TWO_B * D_EMBED];  // normalized rows, bf16
__device__ float g_rowsum[TWO_B];
__device__ float g_pos[B_ROWS];

// ---------------------------------------------------------------------------
// K0: normalize rows -> bf16 Z, fp32 positives, zero row sums
// grid = B_ROWS, block = 128
// ---------------------------------------------------------------------------
__global__ void k_normalize(const float* __restrict__ p1,
                            const float* __restrict__ p2) {
    const int row = blockIdx.x;
    const int t   = threadIdx.x;

    float a = p1[row * D_EMBED + t];
    float b = p2[row * D_EMBED + t];

    float aa = a * a, bb = b * b, ab = a * b;
    #pragma unroll
    for (int off = 16; off > 0; off >>= 1) {
        aa += __shfl_xor_sync(0xffffffffu, aa, off);
        bb += __shfl_xor_sync(0xffffffffu, bb, off);
        ab += __shfl_xor_sync(0xffffffffu, ab, off);
    }
    __shared__ float s[3][4];
    const int warp = t >> 5;
    if ((t & 31) == 0) { s[0][warp] = aa; s[1][warp] = bb; s[2][warp] = ab; }
    __syncthreads();
    const float saa = s[0][0] + s[0][1] + s[0][2] + s[0][3];
    const float sbb = s[1][0] + s[1][1] + s[1][2] + s[1][3];
    const float sab = s[2][0] + s[2][1] + s[2][2] + s[2][3];

    const float n1 = fmaxf(sqrtf(saa), EPS_N);
    const float n2 = fmaxf(sqrtf(sbb), EPS_N);

    g_Zh[row * D_EMBED + t]            = __float2bfloat16(a / n1);
    g_Zh[(B_ROWS + row) * D_EMBED + t] = __float2bfloat16(b / n2);

    if (t == 0) {
        g_pos[row]             = sab / (n1 * n2);
        g_rowsum[row]          = 0.0f;
        g_rowsum[B_ROWS + row] = 0.0f;
    }
}

// ---------------------------------------------------------------------------
// K1: wmma bf16 sim tile 128x128, fused exp + masked row-sum
// grid = (64, 64), block = 256 (8 warps: 2 m-warps x 4 n-warps)
// ---------------------------------------------------------------------------
__global__ __launch_bounds__(256) void k_sim_wmma(void) {
    extern __shared__ char smem[];
    __nv_bfloat16* As = reinterpret_cast<__nv_bfloat16*>(smem);
    __nv_bfloat16* Bs = As + TILE * LDAB;
    float*         Cs = reinterpret_cast<float*>(smem);   // reused after mainloop

    const int tid = threadIdx.x;
    const int wid = tid >> 5;
    const int warp_m = wid >> 2;     // 0..1 -> 64 rows each
    const int warp_n = wid & 3;      // 0..3 -> 32 cols each

    const int I = blockIdx.y * TILE;
    const int J = blockIdx.x * TILE;

    // ---- load tiles (vectorized: 16 uint4 per 128-elem bf16 row) ----
    const uint4* Z4 = reinterpret_cast<const uint4*>(g_Zh);
    #pragma unroll
    for (int idx = tid; idx < TILE * 16; idx += 256) {
        const int row = idx >> 4, c4 = idx & 15;
        *reinterpret_cast<uint4*>(&As[row * LDAB + c4 * 8]) = Z4[(I + row) * 16 + c4];
        *reinterpret_cast<uint4*>(&Bs[row * LDAB + c4 * 8]) = Z4[(J + row) * 16 + c4];
    }
    __syncthreads();

    // ---- mainloop: each warp 64x32, K=128 in 8 slices of 16 ----
    wmma::fragment<wmma::accumulator, 16, 16, 16, float> c[4][2];
    #pragma unroll
    for (int i = 0; i < 4; i++)
        #pragma unroll
        for (int j = 0; j < 2; j++) wmma::fill_fragment(c[i][j], 0.0f);

    #pragma unroll
    for (int k0 = 0; k0 < D_EMBED; k0 += 16) {
        wmma::fragment<wmma::matrix_a, 16, 16, 16, __nv_bfloat16, wmma::row_major> a[4];
        wmma::fragment<wmma::matrix_b, 16, 16, 16, __nv_bfloat16, wmma::col_major> b[2];
        #pragma unroll
        for (int i = 0; i < 4; i++)
            wmma::load_matrix_sync(a[i], &As[(warp_m * 64 + i * 16) * LDAB + k0], LDAB);
        #pragma unroll
        for (int j = 0; j < 2; j++)
            wmma::load_matrix_sync(b[j], &Bs[(warp_n * 32 + j * 16) * LDAB + k0], LDAB);
        #pragma unroll
        for (int i = 0; i < 4; i++)
            #pragma unroll
            for (int j = 0; j < 2; j++)
                wmma::mma_sync(c[i][j], a[i], b[j], c[i][j]);
    }

    // ---- spill accumulators to smem (reuses A/B buffer) ----
    __syncthreads();   // everyone done reading As/Bs
    #pragma unroll
    for (int i = 0; i < 4; i++)
        #pragma unroll
        for (int j = 0; j < 2; j++)
            wmma::store_matrix_sync(
                &Cs[(warp_m * 64 + i * 16) * LDC + warp_n * 32 + j * 16],
                c[i][j], LDC, wmma::mem_row_major);
    __syncthreads();

    // ---- epilogue: 4 threads per row, strided cols (conflict-free LDS) ----
    const int row  = tid >> 2;        // 0..63
    const int q    = tid & 3;         // column phase
    float rp0 = 0.0f, rp1 = 0.0f;
    const int grow0 = I + row;
    const int grow1 = I + 64 + row;
    #pragma unroll
    for (int i = 0; i < 32; i++) {
        const int cc = q + i * 4;
        const int gj = J + cc;
        const float e0 = __expf(INV_T * Cs[row * LDC + cc]);
        const float e1 = __expf(INV_T * Cs[(64 + row) * LDC + cc]);
        rp0 += (grow0 == gj) ? 0.0f : e0;
        rp1 += (grow1 == gj) ? 0.0f : e1;
    }
    #pragma unroll
    for (int off = 1; off < 4; off <<= 1) {
        rp0 += __shfl_xor_sync(0xffffffffu, rp0, off);
        rp1 += __shfl_xor_sync(0xffffffffu, rp1, off);
    }
    if (q == 0) {
        atomicAdd(&g_rowsum[grow0], rp0);
        atomicAdd(&g_rowsum[grow1], rp1);
    }
}

// ---------------------------------------------------------------------------
// K2: loss = sum_i [log(denom_i) - pos_i/T] / (2B)
// ---------------------------------------------------------------------------
__global__ void k_finalize(float* __restrict__ out) {
    __shared__ double sd[1024];
    const int t = threadIdx.x;
    double local = 0.0;
    for (int i = t; i < TWO_B; i += 1024) {
        const double denom = (double)g_rowsum[i];
        const double pos   = (double)g_pos[i & (B_ROWS - 1)];
        local += log(denom) - (double)INV_T * pos;
    }
    sd[t] = local;
    __syncthreads();
    for (int off = 512; off > 0; off >>= 1) {
        if (t < off) sd[t] += sd[t + off];
        __syncthreads();
    }
    if (t == 0) out[0] = (float)(sd[0] / (double)TWO_B);
}

// ---------------------------------------------------------------------------
extern "C" void kernel_launch(void* const* d_in, const int* in_sizes, int n_in,
                              void* d_out, int out_size) {
    const float* p1 = (const float*)d_in[0];
    const float* p2 = (const float*)d_in[1];
    float* out = (float*)d_out;

    cudaFuncSetAttribute(k_sim_wmma, cudaFuncAttributeMaxDynamicSharedMemorySize, SMEM_TOTAL);

    k_normalize<<<B_ROWS, D_EMBED>>>(p1, p2);
    dim3 grid(TWO_B / TILE, TWO_B / TILE);
    k_sim_wmma<<<grid, 256, SMEM_TOTAL>>>();
    k_finalize<<<1, 1024>>>(out);
}

// round 10
// speedup vs baseline: 4.3877x; 1.2752x over previous
#include <cuda_runtime.h>
#include <cuda_bf16.h>
#include <cstdint>
#include <math.h>

#define B_ROWS   4096
#define D_EMBED  128
#define TWO_B    8192
#define INV_T    2.0f
#define EPS_N    1e-8f

#define TILE     128          // CTA tile (M and N)
#define LDAB     136          // bf16 leading dim (272B row stride, 16B-mult)
#define SMEM_TOTAL (2 * TILE * LDAB * 2)   // 69632 B (A + B tiles only)

// Scratch (device globals: allocation-free rule)
__device__ __align__(16) __nv_bfloat16 g_Zh[TWO_B * D_EMBED];  // normalized rows, bf16
__device__ float g_rowsum[TWO_B];
__device__ float g_pos[B_ROWS];

// ---------------- PTX helpers ----------------
__device__ __forceinline__ void ldsm_x4(uint32_t r[4], uint32_t saddr) {
    asm volatile("ldmatrix.sync.aligned.m8n8.x4.shared.b16 {%0,%1,%2,%3}, [%4];"
                 : "=r"(r[0]), "=r"(r[1]), "=r"(r[2]), "=r"(r[3]) : "r"(saddr));
}
__device__ __forceinline__ void mma16816(float c[4], const uint32_t a[4],
                                         uint32_t b0, uint32_t b1) {
    asm volatile(
        "mma.sync.aligned.m16n8k16.row.col.f32.bf16.bf16.f32 "
        "{%0,%1,%2,%3}, {%4,%5,%6,%7}, {%8,%9}, {%0,%1,%2,%3};"
        : "+f"(c[0]), "+f"(c[1]), "+f"(c[2]), "+f"(c[3])
        : "r"(a[0]), "r"(a[1]), "r"(a[2]), "r"(a[3]), "r"(b0), "r"(b1));
}

// ---------------------------------------------------------------------------
// K0: normalize rows -> bf16 Z, fp32 positives, zero row sums
// ---------------------------------------------------------------------------
__global__ void k_normalize(const float* __restrict__ p1,
                            const float* __restrict__ p2) {
    const int row = blockIdx.x;
    const int t   = threadIdx.x;

    float a = p1[row * D_EMBED + t];
    float b = p2[row * D_EMBED + t];

    float aa = a * a, bb = b * b, ab = a * b;
    #pragma unroll
    for (int off = 16; off > 0; off >>= 1) {
        aa += __shfl_xor_sync(0xffffffffu, aa, off);
        bb += __shfl_xor_sync(0xffffffffu, bb, off);
        ab += __shfl_xor_sync(0xffffffffu, ab, off);
    }
    __shared__ float s[3][4];
    const int warp = t >> 5;
    if ((t & 31) == 0) { s[0][warp] = aa; s[1][warp] = bb; s[2][warp] = ab; }
    __syncthreads();
    const float saa = s[0][0] + s[0][1] + s[0][2] + s[0][3];
    const float sbb = s[1][0] + s[1][1] + s[1][2] + s[1][3];
    const float sab = s[2][0] + s[2][1] + s[2][2] + s[2][3];

    const float n1 = fmaxf(sqrtf(saa), EPS_N);
    const float n2 = fmaxf(sqrtf(sbb), EPS_N);

    g_Zh[row * D_EMBED + t]            = __float2bfloat16(a / n1);
    g_Zh[(B_ROWS + row) * D_EMBED + t] = __float2bfloat16(b / n2);

    if (t == 0) {
        g_pos[row]             = sab / (n1 * n2);
        g_rowsum[row]          = 0.0f;
        g_rowsum[B_ROWS + row] = 0.0f;
    }
}

// ---------------------------------------------------------------------------
// K1: mma.sync bf16 sim tile 128x128, register epilogue (exp + masked rowsum)
// grid = (64, 64), block = 256 (8 warps: 2 m-warps x 4 n-warps; warp = 64x32)
// ---------------------------------------------------------------------------
__global__ __launch_bounds__(256, 2) void k_sim_mma(void) {
    extern __shared__ char smem[];
    __nv_bfloat16* As = reinterpret_cast<__nv_bfloat16*>(smem);
    __nv_bfloat16* Bs = As + TILE * LDAB;

    const int tid  = threadIdx.x;
    const int wid  = tid >> 5;
    const int lane = tid & 31;
    const int gid  = lane >> 2;   // group id 0..7
    const int tig  = lane & 3;    // thread-in-group

    const int warp_m = wid >> 2;  // 0..1 -> 64 rows
    const int warp_n = wid & 3;   // 0..3 -> 32 cols

    const int I = blockIdx.y * TILE;
    const int J = blockIdx.x * TILE;

    // ---- load tiles (16 uint4 per 128-elem bf16 row) ----
    const uint4* Z4 = reinterpret_cast<const uint4*>(g_Zh);
    #pragma unroll
    for (int idx = tid; idx < TILE * 16; idx += 256) {
        const int row = idx >> 4, c4 = idx & 15;
        *reinterpret_cast<uint4*>(&As[row * LDAB + c4 * 8]) = Z4[(I + row) * 16 + c4];
        *reinterpret_cast<uint4*>(&Bs[row * LDAB + c4 * 8]) = Z4[(J + row) * 16 + c4];
    }
    __syncthreads();

    const uint32_t As_s = (uint32_t)__cvta_generic_to_shared(As);
    const uint32_t Bs_s = (uint32_t)__cvta_generic_to_shared(Bs);

    // accumulators: 4 m-tiles x 4 n-tiles x 4 regs = 64 floats
    float c[4][4][4];
    #pragma unroll
    for (int mi = 0; mi < 4; mi++)
        #pragma unroll
        for (int nj = 0; nj < 4; nj++)
            #pragma unroll
            for (int r = 0; r < 4; r++) c[mi][nj][r] = 0.0f;

    // ---- mainloop: K=128 in 8 slices of 16 ----
    #pragma unroll
    for (int k0 = 0; k0 < D_EMBED; k0 += 16) {
        uint32_t a[4][4];
        #pragma unroll
        for (int mi = 0; mi < 4; mi++) {
            const int row = warp_m * 64 + mi * 16 + (lane & 15);
            const uint32_t addr = As_s + (uint32_t)((row * LDAB + k0 + (lane >> 4) * 8) * 2);
            ldsm_x4(a[mi], addr);
        }
        uint32_t b[2][4];   // two x4 loads cover 32 n-rows
        #pragma unroll
        for (int h = 0; h < 2; h++) {
            const int row = warp_n * 32 + h * 16 + (lane & 15);
            const uint32_t addr = Bs_s + (uint32_t)((row * LDAB + k0 + (lane >> 4) * 8) * 2);
            ldsm_x4(b[h], addr);
        }
        #pragma unroll
        for (int mi = 0; mi < 4; mi++) {
            #pragma unroll
            for (int h = 0; h < 2; h++) {
                // x4 regs: {r0,r2} -> n-tile h*2, {r1,r3} -> n-tile h*2+1
                mma16816(c[mi][h * 2 + 0], a[mi], b[h][0], b[h][2]);
                mma16816(c[mi][h * 2 + 1], a[mi], b[h][1], b[h][3]);
            }
        }
    }

    // ---- register epilogue: exp(2s), mask diag, per-row partials ----
    float rp[4][2];
    #pragma unroll
    for (int mi = 0; mi < 4; mi++) { rp[mi][0] = 0.0f; rp[mi][1] = 0.0f; }

    #pragma unroll
    for (int mi = 0; mi < 4; mi++) {
        const int gr0 = I + warp_m * 64 + mi * 16 + gid;
        const int gr1 = gr0 + 8;
        #pragma unroll
        for (int nj = 0; nj < 4; nj++) {
            const int gc0 = J + warp_n * 32 + nj * 8 + tig * 2;
            const int gc1 = gc0 + 1;
            float e00 = __expf(INV_T * c[mi][nj][0]);
            float e01 = __expf(INV_T * c[mi][nj][1]);
            float e10 = __expf(INV_T * c[mi][nj][2]);
            float e11 = __expf(INV_T * c[mi][nj][3]);
            if (gr0 == gc0) e00 = 0.0f;
            if (gr0 == gc1) e01 = 0.0f;
            if (gr1 == gc0) e10 = 0.0f;
            if (gr1 == gc1) e11 = 0.0f;
            rp[mi][0] += e00 + e01;
            rp[mi][1] += e10 + e11;
        }
    }
    // reduce across the 4-thread quad (same rows, different cols)
    #pragma unroll
    for (int mi = 0; mi < 4; mi++) {
        #pragma unroll
        for (int h = 0; h < 2; h++) {
            rp[mi][h] += __shfl_xor_sync(0xffffffffu, rp[mi][h], 1);
            rp[mi][h] += __shfl_xor_sync(0xffffffffu, rp[mi][h], 2);
        }
    }
    if (tig == 0) {
        #pragma unroll
        for (int mi = 0; mi < 4; mi++) {
            const int gr = I + warp_m * 64 + mi * 16 + gid;
            atomicAdd(&g_rowsum[gr], rp[mi][0]);
            atomicAdd(&g_rowsum[gr + 8], rp[mi][1]);
        }
    }
}

// ---------------------------------------------------------------------------
// K2: loss = sum_i [log(denom_i) - pos_i/T] / (2B)
// ---------------------------------------------------------------------------
__global__ void k_finalize(float* __restrict__ out) {
    __shared__ double sd[1024];
    const int t = threadIdx.x;
    double local = 0.0;
    for (int i = t; i < TWO_B; i += 1024) {
        const double denom = (double)g_rowsum[i];
        const double pos   = (double)g_pos[i & (B_ROWS - 1)];
        local += log(denom) - (double)INV_T * pos;
    }
    sd[t] = local;
    __syncthreads();
    for (int off = 512; off > 0; off >>= 1) {
        if (t < off) sd[t] += sd[t + off];
        __syncthreads();
    }
    if (t == 0) out[0] = (float)(sd[0] / (double)TWO_B);
}

// ---------------------------------------------------------------------------
extern "C" void kernel_launch(void* const* d_in, const int* in_sizes, int n_in,
                              void* d_out, int out_size) {
    const float* p1 = (const float*)d_in[0];
    const float* p2 = (const float*)d_in[1];
    float* out = (float*)d_out;

    cudaFuncSetAttribute(k_sim_mma, cudaFuncAttributeMaxDynamicSharedMemorySize, SMEM_TOTAL);

    k_normalize<<<B_ROWS, D_EMBED>>>(p1, p2);
    dim3 grid(TWO_B / TILE, TWO_B / TILE);
    k_sim_mma<<<grid, 256, SMEM_TOTAL>>>();
    k_finalize<<<1, 1024>>>(out);
}

// round 14
// speedup vs baseline: 5.0897x; 1.1600x over previous
#include <cuda_runtime.h>
#include <cuda_bf16.h>
#include <cstdint>
#include <math.h>

#define B_ROWS   4096
#define D_EMBED  128
#define TWO_B    8192
#define INV_T    2.0f
#define EPS_N    1e-8f

#define TILE     128          // CTA tile (M and N)
#define LDAB     136          // bf16 leading dim (272B row stride, 16B-mult)
#define SMEM_TOTAL (2 * TILE * LDAB * 2)   // 69632 B
#define NTILE    64           // TWO_B / TILE
#define NBLOCKS  (NTILE * (NTILE + 1) / 2) // 2080 upper-triangle tiles

// Scratch (device globals: allocation-free rule)
__device__ __align__(16) __nv_bfloat16 g_Zh[TWO_B * D_EMBED];
__device__ float g_rowsum[TWO_B];
__device__ float g_pos[B_ROWS];

// ---------------- PTX helpers ----------------
__device__ __forceinline__ void ldsm_x4(uint32_t r[4], uint32_t saddr) {
    asm volatile("ldmatrix.sync.aligned.m8n8.x4.shared.b16 {%0,%1,%2,%3}, [%4];"
                 : "=r"(r[0]), "=r"(r[1]), "=r"(r[2]), "=r"(r[3]) : "r"(saddr));
}
__device__ __forceinline__ void mma16816(float c[4], const uint32_t a[4],
                                         uint32_t b0, uint32_t b1) {
    asm volatile(
        "mma.sync.aligned.m16n8k16.row.col.f32.bf16.bf16.f32 "
        "{%0,%1,%2,%3}, {%4,%5,%6,%7}, {%8,%9}, {%0,%1,%2,%3};"
        : "+f"(c[0]), "+f"(c[1]), "+f"(c[2]), "+f"(c[3])
        : "r"(a[0]), "r"(a[1]), "r"(a[2]), "r"(a[3]), "r"(b0), "r"(b1));
}

// ---------------------------------------------------------------------------
// K0: normalize rows -> bf16 Z, fp32 positives, zero row sums
// ---------------------------------------------------------------------------
__global__ void k_normalize(const float* __restrict__ p1,
                            const float* __restrict__ p2) {
    const int row = blockIdx.x;
    const int t   = threadIdx.x;

    float a = p1[row * D_EMBED + t];
    float b = p2[row * D_EMBED + t];

    float aa = a * a, bb = b * b, ab = a * b;
    #pragma unroll
    for (int off = 16; off > 0; off >>= 1) {
        aa += __shfl_xor_sync(0xffffffffu, aa, off);
        bb += __shfl_xor_sync(0xffffffffu, bb, off);
        ab += __shfl_xor_sync(0xffffffffu, ab, off);
    }
    __shared__ float s[3][4];
    const int warp = t >> 5;
    if ((t & 31) == 0) { s[0][warp] = aa; s[1][warp] = bb; s[2][warp] = ab; }
    __syncthreads();
    const float saa = s[0][0] + s[0][1] + s[0][2] + s[0][3];
    const float sbb = s[1][0] + s[1][1] + s[1][2] + s[1][3];
    const float sab = s[2][0] + s[2][1] + s[2][2] + s[2][3];

    const float n1 = fmaxf(sqrtf(saa), EPS_N);
    const float n2 = fmaxf(sqrtf(sbb), EPS_N);

    g_Zh[row * D_EMBED + t]            = __float2bfloat16(a / n1);
    g_Zh[(B_ROWS + row) * D_EMBED + t] = __float2bfloat16(b / n2);

    if (t == 0) {
        g_pos[row]             = sab / (n1 * n2);
        g_rowsum[row]          = 0.0f;
        g_rowsum[B_ROWS + row] = 0.0f;
    }
}

// ---------------------------------------------------------------------------
// K1: mma.sync bf16 sim, UPPER-TRIANGLE tiles only (symmetry), register
//     epilogue: exp + masked row sums, plus column sums for off-diag tiles.
// grid = 2080, block = 256 (8 warps: 2 m-warps x 4 n-warps; warp = 64x32)
// ---------------------------------------------------------------------------
__global__ __launch_bounds__(256, 2) void k_sim_mma(void) {
    extern __shared__ char smem[];
    __nv_bfloat16* As = reinterpret_cast<__nv_bfloat16*>(smem);
    __nv_bfloat16* Bs = As + TILE * LDAB;

    // --- decode upper-triangle tile (by <= bx) from linear index ---
    const int t_lin = blockIdx.x;
    int by = (int)((129.0 - sqrt(16641.0 - 8.0 * (double)t_lin)) * 0.5);
    while (by * (129 - by) / 2 > t_lin) by--;
    while ((by + 1) * (128 - by) / 2 <= t_lin) by++;   // base(by+1) = (by+1)(128-by)/2
    const int bx = by + (t_lin - by * (129 - by) / 2);

    const int I = by * TILE;     // row tile base
    const int J = bx * TILE;     // col tile base
    const bool diag = (bx == by);

    const int tid  = threadIdx.x;
    const int wid  = tid >> 5;
    const int lane = tid & 31;
    const int gid  = lane >> 2;
    const int tig  = lane & 3;

    const int warp_m = wid >> 2;  // 0..1 -> 64 rows
    const int warp_n = wid & 3;   // 0..3 -> 32 cols

    // ---- load tiles ----
    const uint4* Z4 = reinterpret_cast<const uint4*>(g_Zh);
    #pragma unroll
    for (int idx = tid; idx < TILE * 16; idx += 256) {
        const int row = idx >> 4, c4 = idx & 15;
        *reinterpret_cast<uint4*>(&As[row * LDAB + c4 * 8]) = Z4[(I + row) * 16 + c4];
        *reinterpret_cast<uint4*>(&Bs[row * LDAB + c4 * 8]) = Z4[(J + row) * 16 + c4];
    }
    __syncthreads();

    const uint32_t As_s = (uint32_t)__cvta_generic_to_shared(As);
    const uint32_t Bs_s = (uint32_t)__cvta_generic_to_shared(Bs);

    float c[4][4][4];
    #pragma unroll
    for (int mi = 0; mi < 4; mi++)
        #pragma unroll
        for (int nj = 0; nj < 4; nj++)
            #pragma unroll
            for (int r = 0; r < 4; r++) c[mi][nj][r] = 0.0f;

    // ---- mainloop: K=128 in 8 slices of 16 ----
    #pragma unroll
    for (int k0 = 0; k0 < D_EMBED; k0 += 16) {
        uint32_t a[4][4];
        #pragma unroll
        for (int mi = 0; mi < 4; mi++) {
            const int row = warp_m * 64 + mi * 16 + (lane & 15);
            const uint32_t addr = As_s + (uint32_t)((row * LDAB + k0 + (lane >> 4) * 8) * 2);
            ldsm_x4(a[mi], addr);
        }
        uint32_t b[2][4];
        #pragma unroll
        for (int h = 0; h < 2; h++) {
            const int row = warp_n * 32 + h * 16 + (lane & 15);
            const uint32_t addr = Bs_s + (uint32_t)((row * LDAB + k0 + (lane >> 4) * 8) * 2);
            ldsm_x4(b[h], addr);
        }
        #pragma unroll
        for (int mi = 0; mi < 4; mi++) {
            #pragma unroll
            for (int h = 0; h < 2; h++) {
                mma16816(c[mi][h * 2 + 0], a[mi], b[h][0], b[h][2]);
                mma16816(c[mi][h * 2 + 1], a[mi], b[h][1], b[h][3]);
            }
        }
    }

    // ---- epilogue: exp in place (+ diag mask on diagonal tiles) ----
    #pragma unroll
    for (int mi = 0; mi < 4; mi++) {
        #pragma unroll
        for (int nj = 0; nj < 4; nj++) {
            float e0 = __expf(INV_T * c[mi][nj][0]);
            float e1 = __expf(INV_T * c[mi][nj][1]);
            float e2 = __expf(INV_T * c[mi][nj][2]);
            float e3 = __expf(INV_T * c[mi][nj][3]);
            if (diag) {
                const int r0 = warp_m * 64 + mi * 16 + gid;      // local row
                const int cc = warp_n * 32 + nj * 8 + tig * 2;   // local col
                if (r0 == cc)     e0 = 0.0f;
                if (r0 == cc + 1) e1 = 0.0f;
                if (r0 + 8 == cc)     e2 = 0.0f;
                if (r0 + 8 == cc + 1) e3 = 0.0f;
            }
            c[mi][nj][0] = e0; c[mi][nj][1] = e1;
            c[mi][nj][2] = e2; c[mi][nj][3] = e3;
        }
    }

    // row sums -> rowsum[I + ...]
    #pragma unroll
    for (int mi = 0; mi < 4; mi++) {
        float r0 = 0.0f, r1 = 0.0f;
        #pragma unroll
        for (int nj = 0; nj < 4; nj++) {
            r0 += c[mi][nj][0] + c[mi][nj][1];
            r1 += c[mi][nj][2] + c[mi][nj][3];
        }
        r0 += __shfl_xor_sync(0xffffffffu, r0, 1);
        r0 += __shfl_xor_sync(0xffffffffu, r0, 2);
        r1 += __shfl_xor_sync(0xffffffffu, r1, 1);
        r1 += __shfl_xor_sync(0xffffffffu, r1, 2);
        if (tig == 0) {
            const int gr = I + warp_m * 64 + mi * 16 + gid;
            atomicAdd(&g_rowsum[gr], r0);
            atomicAdd(&g_rowsum[gr + 8], r1);
        }
    }

    // column sums -> rowsum[J + ...] (mirrored tile's rows), off-diag only
    if (!diag) {
        #pragma unroll
        for (int nj = 0; nj < 4; nj++) {
            float c0 = 0.0f, c1 = 0.0f;
            #pragma unroll
            for (int mi = 0; mi < 4; mi++) {
                c0 += c[mi][nj][0] + c[mi][nj][2];
                c1 += c[mi][nj][1] + c[mi][nj][3];
            }
            // reduce over the 8 gid values (lane stride 4)
            c0 += __shfl_xor_sync(0xffffffffu, c0, 4);
            c0 += __shfl_xor_sync(0xffffffffu, c0, 8);
            c0 += __shfl_xor_sync(0xffffffffu, c0, 16);
            c1 += __shfl_xor_sync(0xffffffffu, c1, 4);
            c1 += __shfl_xor_sync(0xffffffffu, c1, 8);
            c1 += __shfl_xor_sync(0xffffffffu, c1, 16);
            if (gid == 0) {
                const int gc = J + warp_n * 32 + nj * 8 + tig * 2;
                atomicAdd(&g_rowsum[gc], c0);
                atomicAdd(&g_rowsum[gc + 1], c1);
            }
        }
    }
}

// ---------------------------------------------------------------------------
// K2: loss = sum_i [log(denom_i) - pos_i/T] / (2B)
// ---------------------------------------------------------------------------
__global__ void k_finalize(float* __restrict__ out) {
    __shared__ double sd[1024];
    const int t = threadIdx.x;
    double local = 0.0;
    for (int i = t; i < TWO_B; i += 1024) {
        const double denom = (double)g_rowsum[i];
        const double pos   = (double)g_pos[i & (B_ROWS - 1)];
        local += log(denom) - (double)INV_T * pos;
    }
    sd[t] = local;
    __syncthreads();
    for (int off = 512; off > 0; off >>= 1) {
        if (t < off) sd[t] += sd[t + off];
        __syncthreads();
    }
    if (t == 0) out[0] = (float)(sd[0] / (double)TWO_B);
}

// ---------------------------------------------------------------------------
extern "C" void kernel_launch(void* const* d_in, const int* in_sizes, int n_in,
                              void* d_out, int out_size) {
    const float* p1 = (const float*)d_in[0];
    const float* p2 = (const float*)d_in[1];
    float* out = (float*)d_out;

    cudaFuncSetAttribute(k_sim_mma, cudaFuncAttributeMaxDynamicSharedMemorySize, SMEM_TOTAL);

    k_normalize<<<B_ROWS, D_EMBED>>>(p1, p2);
    k_sim_mma<<<NBLOCKS, 256, SMEM_TOTAL>>>();
    k_finalize<<<1, 1024>>>(out);
}